// round 13
// baseline (speedup 1.0000x reference)
#include <cuda_runtime.h>
#include <cuda_fp16.h>
#include <cstdint>

// Problem dims
#define BATCH 512
#define TSEQ  256
#define CEMB  384
#define HS    64
#define MTOT  (BATCH * TSEQ)   // 131072

// ---------------- scratch (device globals: allocation-guard safe) -------------
// HALF intermediates; g_q pre-scaled by 1/sqrt(384).
__device__ __half g_q[MTOT * HS];
__device__ __half g_k[MTOT * HS];
__device__ __half g_v[MTOT * HS];

struct alignas(16) H8 { __half2 h[4]; };

__device__ __forceinline__ H8 pack8(float4 a, float4 b) {
    H8 r;
    r.h[0] = __floats2half2_rn(a.x, a.y);
    r.h[1] = __floats2half2_rn(a.z, a.w);
    r.h[2] = __floats2half2_rn(b.x, b.y);
    r.h[3] = __floats2half2_rn(b.z, b.w);
    return r;
}

__device__ __forceinline__ uint32_t h2u(__half2 h) {
    return *reinterpret_cast<uint32_t*>(&h);
}

// ---------------- raw PTX: ldmatrix + mma.m16n8k16 + cp.async ----------------
#define LDM_X4(r0, r1, r2, r3, a) \
    asm volatile("ldmatrix.sync.aligned.m8n8.x4.shared.b16 {%0,%1,%2,%3}, [%4];" \
                 : "=r"(r0), "=r"(r1), "=r"(r2), "=r"(r3) : "r"(a))
#define LDM_X4T(r0, r1, r2, r3, a) \
    asm volatile("ldmatrix.sync.aligned.m8n8.x4.trans.shared.b16 {%0,%1,%2,%3}, [%4];" \
                 : "=r"(r0), "=r"(r1), "=r"(r2), "=r"(r3) : "r"(a))
#define CP_ASYNC16(sa, ga) \
    asm volatile("cp.async.cg.shared.global [%0], [%1], 16;" :: "r"(sa), "l"(ga) : "memory")
#define CP_COMMIT() asm volatile("cp.async.commit_group;" ::: "memory")
#define CP_WAIT0()  asm volatile("cp.async.wait_group 0;" ::: "memory")

__device__ __forceinline__ void mma16816(float* c, uint32_t a0, uint32_t a1,
                                         uint32_t a2, uint32_t a3,
                                         uint32_t b0, uint32_t b1) {
    asm volatile(
        "mma.sync.aligned.m16n8k16.row.col.f32.f16.f16.f32 "
        "{%0,%1,%2,%3}, {%4,%5,%6,%7}, {%8,%9}, {%0,%1,%2,%3};"
        : "+f"(c[0]), "+f"(c[1]), "+f"(c[2]), "+f"(c[3])
        : "r"(a0), "r"(a1), "r"(a2), "r"(a3), "r"(b0), "r"(b1));
}

// =============================================================================
// Kernel 1: QKV projection, raw mma PTX (R12 version, verbatim).
// =============================================================================
#define PBM 64
#define PBN 192
#define PBK 32
#define A_LDH 40
#define B_LDH 200
#define KTILES (CEMB / PBK)   // 12

__global__ __launch_bounds__(256, 2)
void qkv_proj_kernel(const float* __restrict__ x, const float* __restrict__ w)
{
    __shared__ __half As[2][PBM * A_LDH];
    __shared__ __half Bs[2][PBK * B_LDH];

    const int tid    = threadIdx.x;
    const int wid    = tid >> 5;
    const int lane   = tid & 31;
    const int m_base = blockIdx.x * PBM;

    const int wr = (wid & 3) * 16;
    const int wc = (wid >> 2) * 96;

    const int a_row = tid >> 2;
    const int a_c0  = (tid & 3) * 8;
    const int b_row = tid >> 3;
    const int b_c0  = (tid & 7) * 24;

    const float* xA = x + (size_t)(m_base + a_row) * CEMB + a_c0;
    const float* wB = w + (size_t)b_row * PBN + b_c0;

    float4 a_reg[2];
    float4 b_reg[6];

    #pragma unroll
    for (int i = 0; i < 2; i++) a_reg[i] = *(const float4*)(xA + i * 4);
    #pragma unroll
    for (int i = 0; i < 6; i++) b_reg[i] = *(const float4*)(wB + i * 4);

    *(H8*)(As[0] + a_row * A_LDH + a_c0) = pack8(a_reg[0], a_reg[1]);
    #pragma unroll
    for (int i = 0; i < 3; i++)
        *(H8*)(Bs[0] + b_row * B_LDH + b_c0 + i * 8) = pack8(b_reg[2 * i], b_reg[2 * i + 1]);
    __syncthreads();

    float acc[12][4];
    #pragma unroll
    for (int nt = 0; nt < 12; nt++)
        #pragma unroll
        for (int e = 0; e < 4; e++) acc[nt][e] = 0.0f;

    const int lrow8 = (lane & 7) + ((lane >> 3) & 1) * 8;
    const int lcol8 = (lane >> 4) * 8;

    for (int t = 0; t < KTILES; t++) {
        if (t + 1 < KTILES) {
            const int k0 = (t + 1) * PBK;
            #pragma unroll
            for (int i = 0; i < 2; i++) a_reg[i] = *(const float4*)(xA + k0 + i * 4);
            const float* wn2 = wB + (size_t)k0 * PBN;
            #pragma unroll
            for (int i = 0; i < 6; i++) b_reg[i] = *(const float4*)(wn2 + i * 4);
        }

        const uint32_t abase = (uint32_t)__cvta_generic_to_shared(As[t & 1]);
        const uint32_t bbase = (uint32_t)__cvta_generic_to_shared(Bs[t & 1]);

        #pragma unroll
        for (int kk = 0; kk < PBK; kk += 16) {
            uint32_t a0, a1, a2, a3;
            LDM_X4(a0, a1, a2, a3,
                   abase + (uint32_t)((wr + lrow8) * A_LDH + kk + lcol8) * 2);
            #pragma unroll
            for (int np = 0; np < 6; np++) {
                uint32_t b0, b1, b2, b3;
                LDM_X4T(b0, b1, b2, b3,
                        bbase + (uint32_t)((kk + lrow8) * B_LDH + wc + np * 16 + lcol8) * 2);
                mma16816(acc[2 * np],     a0, a1, a2, a3, b0, b1);
                mma16816(acc[2 * np + 1], a0, a1, a2, a3, b2, b3);
            }
        }

        if (t + 1 < KTILES) {
            __half* An = As[(t + 1) & 1];
            __half* Bn = Bs[(t + 1) & 1];
            __syncthreads();
            *(H8*)(An + a_row * A_LDH + a_c0) = pack8(a_reg[0], a_reg[1]);
            #pragma unroll
            for (int i = 0; i < 3; i++)
                *(H8*)(Bn + b_row * B_LDH + b_c0 + i * 8) = pack8(b_reg[2 * i], b_reg[2 * i + 1]);
            __syncthreads();
        }
    }

    const float scale = rsqrtf((float)CEMB);
    const size_t row0 = (size_t)m_base + wr + (lane >> 2);
    const int    c0   = 2 * (lane & 3);
    #pragma unroll
    for (int nt = 0; nt < 12; nt++) {
        const int col   = wc + nt * 8 + c0;
        const int slice = col >> 6;          // 0,1,2 -> q,k,v
        const int lcol  = col & 63;
        __half* dst = (slice == 0) ? g_q : ((slice == 1) ? g_k : g_v);
        float f0 = acc[nt][0], f1 = acc[nt][1], f2 = acc[nt][2], f3 = acc[nt][3];
        if (slice == 0) { f0 *= scale; f1 *= scale; f2 *= scale; f3 *= scale; }
        *(__half2*)(dst + row0 * HS + lcol)       = __floats2half2_rn(f0, f1);
        *(__half2*)(dst + (row0 + 8) * HS + lcol) = __floats2half2_rn(f2, f3);
    }
}

// =============================================================================
// Kernel 2: FlashAttention-style fused causal attention.
// 128 threads / CTA, 4 CTAs/SM target. cp.async K/V/Q staging (no staging
// registers), x4 ldmatrix in both mainloops, S/P in registers,
// deferred normalization, one barrier per tile.
// =============================================================================
#define KV_LDH 72
#define ATT_SMEM_BYTES (4 * 64 * KV_LDH * 2)   // 36864

__global__ __launch_bounds__(128, 4)
void attn_kernel(float* __restrict__ out)
{
    extern __shared__ __half kvsm[];
    const uint32_t smbase = (uint32_t)__cvta_generic_to_shared(kvsm);
    const uint32_t kbu[2] = { smbase,                       smbase + 64 * KV_LDH * 2 };
    const uint32_t vbu[2] = { smbase + 2 * 64 * KV_LDH * 2, smbase + 3 * 64 * KV_LDH * 2 };

    const int tid  = threadIdx.x;
    const int w    = tid >> 5;          // warp 0..3 -> q rows w*16..+15
    const int lane = tid & 31;
    const int qt   = blockIdx.x;
    const int b    = blockIdx.y;

    const __half* Qg = g_q + (size_t)b * TSEQ * HS + (size_t)qt * 64 * HS;
    const __half* Kg = g_k + (size_t)b * TSEQ * HS;
    const __half* Vg = g_v + (size_t)b * TSEQ * HS;
    float*        Og = out + (size_t)b * TSEQ * HS + (size_t)qt * 64 * HS;

    // staging: fidx = tid + j*128; row = fidx>>3; c = (fidx&7)*8 halves
    const int s_row = tid >> 3;                 // 0..15 (+16 per j)
    const int s_c   = (tid & 7) * 8;
    const uint32_t s_off = (uint32_t)(s_row * KV_LDH + s_c) * 2;
    const int g_off = s_row * HS + s_c;

    // ---- prologue: cp.async K0 -> Kb0, V0 -> Vb0, Q -> Vb1 ----
    #pragma unroll
    for (int j = 0; j < 4; j++) {
        const uint32_t so = s_off + (uint32_t)(j * 16 * KV_LDH) * 2;
        const int go = g_off + j * 16 * HS;
        CP_ASYNC16(kbu[0] + so, Kg + go);
        CP_ASYNC16(vbu[0] + so, Vg + go);
        CP_ASYNC16(vbu[1] + so, Qg + go);
    }
    CP_COMMIT();
    CP_WAIT0();
    __syncthreads();

    // ---- load Q fragments (4 k-chunks x 4 regs) from Vb1, persistent ----
    uint32_t qf[4][4];
    const int lrow8 = (lane & 7) + ((lane >> 3) & 1) * 8;   // 0..15
    const int lcol8 = (lane >> 4) * 8;                       // 0 or 8
    {
        #pragma unroll
        for (int kc = 0; kc < 4; kc++) {
            LDM_X4(qf[kc][0], qf[kc][1], qf[kc][2], qf[kc][3],
                   vbu[1] + (uint32_t)((w * 16 + lrow8) * KV_LDH + kc * 16 + lcol8) * 2);
        }
    }
    __syncthreads();   // all qf reads done before kt=0 prefetch overwrites Vb1

    float oacc[8][4];
    #pragma unroll
    for (int n = 0; n < 8; n++)
        #pragma unroll
        for (int e = 0; e < 4; e++) oacc[n][e] = 0.0f;
    float sum0 = 0.0f, sum1 = 0.0f;

    const int row0 = w * 16 + (lane >> 2);   // q row for c0/c1; +8 for c2/c3
    const int kq   = 2 * (lane & 3);         // key sub-index within n-tile

    for (int kt = 0; kt <= qt; kt++) {
        const int cur = kt & 1;
        const bool diag = (kt == qt);
        const int ntmax = diag ? (2 * w + 2) : 8;

        // ---- prefetch next K/V tiles via cp.async (buffers last read kt-1) ----
        if (kt < qt) {
            const int gbase = (kt + 1) * 64 * HS + g_off;
            #pragma unroll
            for (int j = 0; j < 4; j++) {
                const uint32_t so = s_off + (uint32_t)(j * 16 * KV_LDH) * 2;
                const int go = gbase + j * 16 * HS;
                CP_ASYNC16(kbu[cur ^ 1] + so, Kg + go);
                CP_ASYNC16(vbu[cur ^ 1] + so, Vg + go);
            }
            CP_COMMIT();
        }

        // ---- S = Q K^T (x4 ldmatrix: 2 n-tiles per load) ----
        float sacc[8][4];
        #pragma unroll
        for (int nt = 0; nt < 8; nt += 2) {
            if (nt < ntmax) {
                #pragma unroll
                for (int e = 0; e < 4; e++) { sacc[nt][e] = 0.0f; sacc[nt + 1][e] = 0.0f; }
                #pragma unroll
                for (int kc = 0; kc < 4; kc++) {
                    uint32_t b0, b1, b2, b3;
                    LDM_X4(b0, b1, b2, b3,
                           kbu[cur] + (uint32_t)((nt * 8 + lrow8) * KV_LDH + kc * 16 + lcol8) * 2);
                    mma16816(sacc[nt],     qf[kc][0], qf[kc][1], qf[kc][2], qf[kc][3], b0, b2);
                    mma16816(sacc[nt + 1], qf[kc][0], qf[kc][1], qf[kc][2], qf[kc][3], b1, b3);
                }
            }
        }

        // ---- exp + row sums (mask on diagonal tile) ----
        #pragma unroll
        for (int nt = 0; nt < 8; nt++) {
            if (nt < ntmax) {
                if (diag && nt >= 2 * w) {
                    const int k0 = nt * 8 + kq;
                    sacc[nt][0] = (k0     <= row0)     ? __expf(sacc[nt][0]) : 0.0f;
                    sacc[nt][1] = (k0 + 1 <= row0)     ? __expf(sacc[nt][1]) : 0.0f;
                    sacc[nt][2] = (k0     <= row0 + 8) ? __expf(sacc[nt][2]) : 0.0f;
                    sacc[nt][3] = (k0 + 1 <= row0 + 8) ? __expf(sacc[nt][3]) : 0.0f;
                } else {
                    sacc[nt][0] = __expf(sacc[nt][0]);
                    sacc[nt][1] = __expf(sacc[nt][1]);
                    sacc[nt][2] = __expf(sacc[nt][2]);
                    sacc[nt][3] = __expf(sacc[nt][3]);
                }
                sum0 += sacc[nt][0] + sacc[nt][1];
                sum1 += sacc[nt][2] + sacc[nt][3];
            }
        }

        // ---- O += P V (x4.trans ldmatrix: 2 n-tiles per load) ----
        const int kcmax = diag ? (w + 1) : 4;
        #pragma unroll
        for (int kc = 0; kc < 4; kc++) {
            if (kc < kcmax) {
                const uint32_t p0 = h2u(__floats2half2_rn(sacc[2 * kc][0],     sacc[2 * kc][1]));
                const uint32_t p1 = h2u(__floats2half2_rn(sacc[2 * kc][2],     sacc[2 * kc][3]));
                const uint32_t p2 = h2u(__floats2half2_rn(sacc[2 * kc + 1][0], sacc[2 * kc + 1][1]));
                const uint32_t p3 = h2u(__floats2half2_rn(sacc[2 * kc + 1][2], sacc[2 * kc + 1][3]));
                #pragma unroll
                for (int nt = 0; nt < 8; nt += 2) {
                    uint32_t b0, b1, b2, b3;
                    LDM_X4T(b0, b1, b2, b3,
                            vbu[cur] + (uint32_t)((kc * 16 + lrow8) * KV_LDH + nt * 8 + lcol8) * 2);
                    mma16816(oacc[nt],     p0, p1, p2, p3, b0, b1);
                    mma16816(oacc[nt + 1], p0, p1, p2, p3, b2, b3);
                }
            }
        }

        if (kt < qt) CP_WAIT0();
        __syncthreads();
    }

    // ---- finalize: quad-reduce sums, normalize, store ----
    #pragma unroll
    for (int off = 1; off <= 2; off <<= 1) {
        sum0 += __shfl_xor_sync(0xffffffffu, sum0, off);
        sum1 += __shfl_xor_sync(0xffffffffu, sum1, off);
    }
    const float inv0 = 1.0f / sum0;
    const float inv1 = 1.0f / sum1;

    float* o0 = Og + (size_t)row0 * HS + kq;
    float* o1 = o0 + 8 * HS;
    #pragma unroll
    for (int nt = 0; nt < 8; nt++) {
        *(float2*)(o0 + nt * 8) = make_float2(oacc[nt][0] * inv0, oacc[nt][1] * inv0);
        *(float2*)(o1 + nt * 8) = make_float2(oacc[nt][2] * inv1, oacc[nt][3] * inv1);
    }
}

// =============================================================================
extern "C" void kernel_launch(void* const* d_in, const int* in_sizes, int n_in,
                              void* d_out, int out_size)
{
    const float* x = (const float*)d_in[0];     // [512,256,384]
    const float* w = (const float*)d_in[1];     // [384,192]
    float* out = (float*)d_out;                 // [512,256,64]

    (void)in_sizes; (void)n_in; (void)out_size;

    static bool attr_set = false;
    if (!attr_set) {
        cudaFuncSetAttribute(attn_kernel, cudaFuncAttributeMaxDynamicSharedMemorySize,
                             ATT_SMEM_BYTES);
        attr_set = true;
    }

    qkv_proj_kernel<<<MTOT / PBM, 256>>>(x, w);
    attn_kernel<<<dim3(4, BATCH), 128, ATT_SMEM_BYTES>>>(out);
}

// round 16
// speedup vs baseline: 1.6080x; 1.6080x over previous
#include <cuda_runtime.h>
#include <cuda_fp16.h>
#include <cstdint>

// Problem dims
#define BATCH 512
#define TSEQ  256
#define CEMB  384
#define HS    64
#define MTOT  (BATCH * TSEQ)   // 131072

// ---------------- scratch (device globals: allocation-guard safe) -------------
// HALF intermediates; g_q pre-scaled by 1/sqrt(384).
__device__ __half g_q[MTOT * HS];
__device__ __half g_k[MTOT * HS];
__device__ __half g_v[MTOT * HS];

struct alignas(16) H8 { __half2 h[4]; };

__device__ __forceinline__ H8 pack8(float4 a, float4 b) {
    H8 r;
    r.h[0] = __floats2half2_rn(a.x, a.y);
    r.h[1] = __floats2half2_rn(a.z, a.w);
    r.h[2] = __floats2half2_rn(b.x, b.y);
    r.h[3] = __floats2half2_rn(b.z, b.w);
    return r;
}

__device__ __forceinline__ uint32_t h2u(__half2 h) {
    return *reinterpret_cast<uint32_t*>(&h);
}

// ---------------- raw PTX: ldmatrix + mma.m16n8k16 + cp.async ----------------
#define LDM_X4(r0, r1, r2, r3, a) \
    asm volatile("ldmatrix.sync.aligned.m8n8.x4.shared.b16 {%0,%1,%2,%3}, [%4];" \
                 : "=r"(r0), "=r"(r1), "=r"(r2), "=r"(r3) : "r"(a))
#define LDM_X4T(r0, r1, r2, r3, a) \
    asm volatile("ldmatrix.sync.aligned.m8n8.x4.trans.shared.b16 {%0,%1,%2,%3}, [%4];" \
                 : "=r"(r0), "=r"(r1), "=r"(r2), "=r"(r3) : "r"(a))
#define CP_ASYNC16(sa, ga) \
    asm volatile("cp.async.cg.shared.global [%0], [%1], 16;" :: "r"(sa), "l"(ga) : "memory")
#define CP_COMMIT() asm volatile("cp.async.commit_group;" ::: "memory")
#define CP_WAIT0()  asm volatile("cp.async.wait_group 0;" ::: "memory")

__device__ __forceinline__ void mma16816(float* c, uint32_t a0, uint32_t a1,
                                         uint32_t a2, uint32_t a3,
                                         uint32_t b0, uint32_t b1) {
    asm volatile(
        "mma.sync.aligned.m16n8k16.row.col.f32.f16.f16.f32 "
        "{%0,%1,%2,%3}, {%4,%5,%6,%7}, {%8,%9}, {%0,%1,%2,%3};"
        : "+f"(c[0]), "+f"(c[1]), "+f"(c[2]), "+f"(c[3])
        : "r"(a0), "r"(a1), "r"(a2), "r"(a3), "r"(b0), "r"(b1));
}

// =============================================================================
// Kernel 1: QKV projection, raw mma PTX.  qkv = x @ w  (M=131072, N=192, K=384)
// 256 threads, CTA tile 64x192, BK=32, double-buffered half smem + reg prefetch.
// 8 warps = 2 row-groups (32 rows) x 4 col-groups (48 cols): per k16 step,
// 2x ldmatrix.x4 (A) + 3x ldmatrix.x4.trans (B) feed 12 MMAs (0.42 loads/MMA).
// Epilogue: known m16n8 layout -> direct half2 STG (q scaled by 1/sqrt(384)).
// =============================================================================
#define PBM 64
#define PBN 192
#define PBK 32
#define A_LDH 40
#define B_LDH 200
#define KTILES (CEMB / PBK)   // 12

__global__ __launch_bounds__(256, 2)
void qkv_proj_kernel(const float* __restrict__ x, const float* __restrict__ w)
{
    __shared__ __half As[2][PBM * A_LDH];
    __shared__ __half Bs[2][PBK * B_LDH];

    const int tid    = threadIdx.x;
    const int wid    = tid >> 5;
    const int lane   = tid & 31;
    const int m_base = blockIdx.x * PBM;

    const int wr = (wid & 1) * 32;       // warp row base (0 or 32)
    const int wc = (wid >> 1) * 48;      // warp col base (0,48,96,144)

    const int a_row = tid >> 2;
    const int a_c0  = (tid & 3) * 8;
    const int b_row = tid >> 3;
    const int b_c0  = (tid & 7) * 24;

    const float* xA = x + (size_t)(m_base + a_row) * CEMB + a_c0;
    const float* wB = w + (size_t)b_row * PBN + b_c0;

    float4 a_reg[2];
    float4 b_reg[6];

    #pragma unroll
    for (int i = 0; i < 2; i++) a_reg[i] = *(const float4*)(xA + i * 4);
    #pragma unroll
    for (int i = 0; i < 6; i++) b_reg[i] = *(const float4*)(wB + i * 4);

    *(H8*)(As[0] + a_row * A_LDH + a_c0) = pack8(a_reg[0], a_reg[1]);
    #pragma unroll
    for (int i = 0; i < 3; i++)
        *(H8*)(Bs[0] + b_row * B_LDH + b_c0 + i * 8) = pack8(b_reg[2 * i], b_reg[2 * i + 1]);
    __syncthreads();

    float acc[2][6][4];
    #pragma unroll
    for (int m = 0; m < 2; m++)
        #pragma unroll
        for (int nt = 0; nt < 6; nt++)
            #pragma unroll
            for (int e = 0; e < 4; e++) acc[m][nt][e] = 0.0f;

    const int lrow8 = (lane & 7) + ((lane >> 3) & 1) * 8;   // 0..15
    const int lcol8 = (lane >> 4) * 8;                       // 0 or 8

    for (int t = 0; t < KTILES; t++) {
        if (t + 1 < KTILES) {
            const int k0 = (t + 1) * PBK;
            #pragma unroll
            for (int i = 0; i < 2; i++) a_reg[i] = *(const float4*)(xA + k0 + i * 4);
            const float* wn2 = wB + (size_t)k0 * PBN;
            #pragma unroll
            for (int i = 0; i < 6; i++) b_reg[i] = *(const float4*)(wn2 + i * 4);
        }

        const uint32_t abase = (uint32_t)__cvta_generic_to_shared(As[t & 1]);
        const uint32_t bbase = (uint32_t)__cvta_generic_to_shared(Bs[t & 1]);

        #pragma unroll
        for (int kk = 0; kk < PBK; kk += 16) {
            uint32_t af[2][4];
            #pragma unroll
            for (int m = 0; m < 2; m++)
                LDM_X4(af[m][0], af[m][1], af[m][2], af[m][3],
                       abase + (uint32_t)((wr + m * 16 + lrow8) * A_LDH + kk + lcol8) * 2);
            #pragma unroll
            for (int np = 0; np < 3; np++) {
                uint32_t b0, b1, b2, b3;
                LDM_X4T(b0, b1, b2, b3,
                        bbase + (uint32_t)((kk + lrow8) * B_LDH + wc + np * 16 + lcol8) * 2);
                #pragma unroll
                for (int m = 0; m < 2; m++) {
                    mma16816(acc[m][2 * np],     af[m][0], af[m][1], af[m][2], af[m][3], b0, b1);
                    mma16816(acc[m][2 * np + 1], af[m][0], af[m][1], af[m][2], af[m][3], b2, b3);
                }
            }
        }

        if (t + 1 < KTILES) {
            __half* An = As[(t + 1) & 1];
            __half* Bn = Bs[(t + 1) & 1];
            __syncthreads();
            *(H8*)(An + a_row * A_LDH + a_c0) = pack8(a_reg[0], a_reg[1]);
            #pragma unroll
            for (int i = 0; i < 3; i++)
                *(H8*)(Bn + b_row * B_LDH + b_c0 + i * 8) = pack8(b_reg[2 * i], b_reg[2 * i + 1]);
            __syncthreads();
        }
    }

    // ---- epilogue: m16n8 acc layout -> half2 stores; q scaled ----
    const float scale = rsqrtf((float)CEMB);
    const int c0 = 2 * (lane & 3);
    #pragma unroll
    for (int m = 0; m < 2; m++) {
        const size_t row0 = (size_t)m_base + wr + m * 16 + (lane >> 2);
        #pragma unroll
        for (int nt = 0; nt < 6; nt++) {
            const int col   = wc + nt * 8 + c0;
            const int slice = col >> 6;          // 0,1,2 -> q,k,v
            const int lcol  = col & 63;
            __half* dst = (slice == 0) ? g_q : ((slice == 1) ? g_k : g_v);
            float f0 = acc[m][nt][0], f1 = acc[m][nt][1];
            float f2 = acc[m][nt][2], f3 = acc[m][nt][3];
            if (slice == 0) { f0 *= scale; f1 *= scale; f2 *= scale; f3 *= scale; }
            *(__half2*)(dst + row0 * HS + lcol)       = __floats2half2_rn(f0, f1);
            *(__half2*)(dst + (row0 + 8) * HS + lcol) = __floats2half2_rn(f2, f3);
        }
    }
}

// =============================================================================
// Kernel 2: FlashAttention-style fused causal attention (R13 version verbatim).
// 128 threads / CTA. cp.async K/V/Q staging, x4 ldmatrix, S/P in registers,
// deferred normalization, one barrier per tile.
// =============================================================================
#define KV_LDH 72
#define ATT_SMEM_BYTES (4 * 64 * KV_LDH * 2)   // 36864

__global__ __launch_bounds__(128, 4)
void attn_kernel(float* __restrict__ out)
{
    extern __shared__ __half kvsm[];
    const uint32_t smbase = (uint32_t)__cvta_generic_to_shared(kvsm);
    const uint32_t kbu[2] = { smbase,                       smbase + 64 * KV_LDH * 2 };
    const uint32_t vbu[2] = { smbase + 2 * 64 * KV_LDH * 2, smbase + 3 * 64 * KV_LDH * 2 };

    const int tid  = threadIdx.x;
    const int w    = tid >> 5;          // warp 0..3 -> q rows w*16..+15
    const int lane = tid & 31;
    const int qt   = blockIdx.x;
    const int b    = blockIdx.y;

    const __half* Qg = g_q + (size_t)b * TSEQ * HS + (size_t)qt * 64 * HS;
    const __half* Kg = g_k + (size_t)b * TSEQ * HS;
    const __half* Vg = g_v + (size_t)b * TSEQ * HS;
    float*        Og = out + (size_t)b * TSEQ * HS + (size_t)qt * 64 * HS;

    const int s_row = tid >> 3;                 // 0..15 (+16 per j)
    const int s_c   = (tid & 7) * 8;
    const uint32_t s_off = (uint32_t)(s_row * KV_LDH + s_c) * 2;
    const int g_off = s_row * HS + s_c;

    // ---- prologue: cp.async K0 -> Kb0, V0 -> Vb0, Q -> Vb1 ----
    #pragma unroll
    for (int j = 0; j < 4; j++) {
        const uint32_t so = s_off + (uint32_t)(j * 16 * KV_LDH) * 2;
        const int go = g_off + j * 16 * HS;
        CP_ASYNC16(kbu[0] + so, Kg + go);
        CP_ASYNC16(vbu[0] + so, Vg + go);
        CP_ASYNC16(vbu[1] + so, Qg + go);
    }
    CP_COMMIT();
    CP_WAIT0();
    __syncthreads();

    // ---- load Q fragments (4 k-chunks x 4 regs) from Vb1, persistent ----
    uint32_t qf[4][4];
    const int lrow8 = (lane & 7) + ((lane >> 3) & 1) * 8;   // 0..15
    const int lcol8 = (lane >> 4) * 8;                       // 0 or 8
    {
        #pragma unroll
        for (int kc = 0; kc < 4; kc++) {
            LDM_X4(qf[kc][0], qf[kc][1], qf[kc][2], qf[kc][3],
                   vbu[1] + (uint32_t)((w * 16 + lrow8) * KV_LDH + kc * 16 + lcol8) * 2);
        }
    }
    __syncthreads();   // all qf reads done before kt=0 prefetch overwrites Vb1

    float oacc[8][4];
    #pragma unroll
    for (int n = 0; n < 8; n++)
        #pragma unroll
        for (int e = 0; e < 4; e++) oacc[n][e] = 0.0f;
    float sum0 = 0.0f, sum1 = 0.0f;

    const int row0 = w * 16 + (lane >> 2);   // q row for c0/c1; +8 for c2/c3
    const int kq   = 2 * (lane & 3);         // key sub-index within n-tile

    for (int kt = 0; kt <= qt; kt++) {
        const int cur = kt & 1;
        const bool diag = (kt == qt);
        const int ntmax = diag ? (2 * w + 2) : 8;

        if (kt < qt) {
            const int gbase = (kt + 1) * 64 * HS + g_off;
            #pragma unroll
            for (int j = 0; j < 4; j++) {
                const uint32_t so = s_off + (uint32_t)(j * 16 * KV_LDH) * 2;
                const int go = gbase + j * 16 * HS;
                CP_ASYNC16(kbu[cur ^ 1] + so, Kg + go);
                CP_ASYNC16(vbu[cur ^ 1] + so, Vg + go);
            }
            CP_COMMIT();
        }

        // ---- S = Q K^T (x4 ldmatrix: 2 n-tiles per load) ----
        float sacc[8][4];
        #pragma unroll
        for (int nt = 0; nt < 8; nt += 2) {
            if (nt < ntmax) {
                #pragma unroll
                for (int e = 0; e < 4; e++) { sacc[nt][e] = 0.0f; sacc[nt + 1][e] = 0.0f; }
                #pragma unroll
                for (int kc = 0; kc < 4; kc++) {
                    uint32_t b0, b1, b2, b3;
                    LDM_X4(b0, b1, b2, b3,
                           kbu[cur] + (uint32_t)((nt * 8 + lrow8) * KV_LDH + kc * 16 + lcol8) * 2);
                    mma16816(sacc[nt],     qf[kc][0], qf[kc][1], qf[kc][2], qf[kc][3], b0, b2);
                    mma16816(sacc[nt + 1], qf[kc][0], qf[kc][1], qf[kc][2], qf[kc][3], b1, b3);
                }
            }
        }

        // ---- exp + row sums (mask on diagonal tile) ----
        #pragma unroll
        for (int nt = 0; nt < 8; nt++) {
            if (nt < ntmax) {
                if (diag && nt >= 2 * w) {
                    const int k0 = nt * 8 + kq;
                    sacc[nt][0] = (k0     <= row0)     ? __expf(sacc[nt][0]) : 0.0f;
                    sacc[nt][1] = (k0 + 1 <= row0)     ? __expf(sacc[nt][1]) : 0.0f;
                    sacc[nt][2] = (k0     <= row0 + 8) ? __expf(sacc[nt][2]) : 0.0f;
                    sacc[nt][3] = (k0 + 1 <= row0 + 8) ? __expf(sacc[nt][3]) : 0.0f;
                } else {
                    sacc[nt][0] = __expf(sacc[nt][0]);
                    sacc[nt][1] = __expf(sacc[nt][1]);
                    sacc[nt][2] = __expf(sacc[nt][2]);
                    sacc[nt][3] = __expf(sacc[nt][3]);
                }
                sum0 += sacc[nt][0] + sacc[nt][1];
                sum1 += sacc[nt][2] + sacc[nt][3];
            }
        }

        // ---- O += P V (x4.trans ldmatrix: 2 n-tiles per load) ----
        const int kcmax = diag ? (w + 1) : 4;
        #pragma unroll
        for (int kc = 0; kc < 4; kc++) {
            if (kc < kcmax) {
                const uint32_t p0 = h2u(__floats2half2_rn(sacc[2 * kc][0],     sacc[2 * kc][1]));
                const uint32_t p1 = h2u(__floats2half2_rn(sacc[2 * kc][2],     sacc[2 * kc][3]));
                const uint32_t p2 = h2u(__floats2half2_rn(sacc[2 * kc + 1][0], sacc[2 * kc + 1][1]));
                const uint32_t p3 = h2u(__floats2half2_rn(sacc[2 * kc + 1][2], sacc[2 * kc + 1][3]));
                #pragma unroll
                for (int nt = 0; nt < 8; nt += 2) {
                    uint32_t b0, b1, b2, b3;
                    LDM_X4T(b0, b1, b2, b3,
                            vbu[cur] + (uint32_t)((kc * 16 + lrow8) * KV_LDH + nt * 8 + lcol8) * 2);
                    mma16816(oacc[nt],     p0, p1, p2, p3, b0, b1);
                    mma16816(oacc[nt + 1], p0, p1, p2, p3, b2, b3);
                }
            }
        }

        if (kt < qt) CP_WAIT0();
        __syncthreads();
    }

    // ---- finalize: quad-reduce sums, normalize, store ----
    #pragma unroll
    for (int off = 1; off <= 2; off <<= 1) {
        sum0 += __shfl_xor_sync(0xffffffffu, sum0, off);
        sum1 += __shfl_xor_sync(0xffffffffu, sum1, off);
    }
    const float inv0 = 1.0f / sum0;
    const float inv1 = 1.0f / sum1;

    float* o0 = Og + (size_t)row0 * HS + kq;
    float* o1 = o0 + 8 * HS;
    #pragma unroll
    for (int nt = 0; nt < 8; nt++) {
        *(float2*)(o0 + nt * 8) = make_float2(oacc[nt][0] * inv0, oacc[nt][1] * inv0);
        *(float2*)(o1 + nt * 8) = make_float2(oacc[nt][2] * inv1, oacc[nt][3] * inv1);
    }
}

// =============================================================================
extern "C" void kernel_launch(void* const* d_in, const int* in_sizes, int n_in,
                              void* d_out, int out_size)
{
    const float* x = (const float*)d_in[0];     // [512,256,384]
    const float* w = (const float*)d_in[1];     // [384,192]
    float* out = (float*)d_out;                 // [512,256,64]

    (void)in_sizes; (void)n_in; (void)out_size;

    static bool attr_set = false;
    if (!attr_set) {
        cudaFuncSetAttribute(attn_kernel, cudaFuncAttributeMaxDynamicSharedMemorySize,
                             ATT_SMEM_BYTES);
        attr_set = true;
    }

    qkv_proj_kernel<<<MTOT / PBM, 256>>>(x, w);
    attn_kernel<<<dim3(4, BATCH), 128, ATT_SMEM_BYTES>>>(out);
}